// round 1
// baseline (speedup 1.0000x reference)
#include <cuda_runtime.h>
#include <math.h>

#define BB 8
#define NN 2048
#define MM 2048
#define STRIDE 512
#define NITER 100

#define KFLOOR 1.9287498479639178e-22f   /* fp32(exp(-50)) */
#define MUV    4.8828125e-4f             /* 1/2048 */
#define EPSDIV 1e-8f

static __device__ __forceinline__ float uaf(unsigned x) { return __uint_as_float(x); }

// ---- static device scratch (no allocations allowed) ----
__device__ uint2 g_rell[(size_t)BB * STRIDE * NN];  // row-ELL: entry k of row i at [b][k][i] = (j, Ktilde)
__device__ uint2 g_cell[(size_t)BB * STRIDE * MM];  // col-ELL: entry k of col j at [b][k][j] = (i, Ktilde)
__device__ int   g_rcnt[BB * NN];
__device__ int   g_ccnt[BB * MM];
__device__ float g_u[BB * NN];
__device__ float g_v[BB * MM];
__device__ float g_accum;

// ---------------------------------------------------------------------------
__global__ void init_kernel() {
    int t = blockIdx.x * blockDim.x + threadIdx.x;
    if (t < BB * NN) g_rcnt[t] = 0;
    if (t < BB * MM) g_ccnt[t] = 0;
    if (t == 0) g_accum = 0.0f;
}

// ---------------------------------------------------------------------------
// Build sparse correction lists: entries where d^2 < 0.25 (i.e. 100*d < 50).
// Everything else has K == exp(-50) exactly (same as the reference's clamp).
__global__ void build_kernel(const float* __restrict__ src, const float* __restrict__ tgt) {
    const int b = blockIdx.y;
    __shared__ float tx[MM], ty[MM], tz[MM];
    const float* T = tgt + (size_t)b * MM * 3;
    for (int j = threadIdx.x; j < MM; j += blockDim.x) {
        tx[j] = T[3 * j + 0];
        ty[j] = T[3 * j + 1];
        tz[j] = T[3 * j + 2];
    }
    __syncthreads();

    const int warp = threadIdx.x >> 5, lane = threadIdx.x & 31;
    const int nwarps = blockDim.x >> 5;
    const int rows_per_cta = NN / gridDim.x;
    const int row0 = blockIdx.x * rows_per_cta;
    const float* S = src + (size_t)b * NN * 3;
    uint2* rell = g_rell + (size_t)b * STRIDE * NN;
    uint2* cell = g_cell + (size_t)b * STRIDE * MM;

    for (int i = row0 + warp; i < row0 + rows_per_cta; i += nwarps) {
        const float sx = S[3 * i + 0], sy = S[3 * i + 1], sz = S[3 * i + 2];
        int rbase = 0;
        for (int j0 = 0; j0 < MM; j0 += 32) {
            const int j = j0 + lane;
            float dx = sx - tx[j];
            float dy = sy - ty[j];
            float dz = sz - tz[j];
            float s = fmaf(dx, dx, fmaf(dy, dy, dz * dz));
            bool pred = (s < 0.25f);
            unsigned mask = __ballot_sync(0xffffffffu, pred);
            if (pred) {
                float kt = expf(-100.0f * sqrtf(s)) - KFLOOR;
                int k = rbase + __popc(mask & ((1u << lane) - 1u));
                if (k < STRIDE)
                    rell[(size_t)k * NN + i] = make_uint2((unsigned)j, __float_as_uint(kt));
                int kc = atomicAdd(&g_ccnt[b * MM + j], 1);
                if (kc < STRIDE)
                    cell[(size_t)kc * MM + j] = make_uint2((unsigned)i, __float_as_uint(kt));
            }
            rbase += __popc(mask);
        }
        g_rcnt[b * NN + i] = (rbase < STRIDE) ? rbase : STRIDE;
    }
}

// ---------------------------------------------------------------------------
__device__ __forceinline__ float block_reduce_sum(float val, float* red) {
#pragma unroll
    for (int o = 16; o > 0; o >>= 1) val += __shfl_xor_sync(0xffffffffu, val, o);
    const int lane = threadIdx.x & 31, warp = threadIdx.x >> 5;
    if (lane == 0) red[warp] = val;
    __syncthreads();
    float r = 0.0f;
    if (warp == 0) {
        r = red[lane];  // exactly 32 warps (1024 threads)
#pragma unroll
        for (int o = 16; o > 0; o >>= 1) r += __shfl_xor_sync(0xffffffffu, r, o);
    }
    return r;  // valid on warp 0
}

// One CTA per batch. u, v, counts in SMEM. Per iteration:
//   u_i = mu / max(KFLOOR*S_v + sparse_row_i . v, 1e-8)
//   v_j = nu / max(KFLOOR*S_u + sparse_col_j . u, 1e-8)
__global__ void __launch_bounds__(1024, 1) sinkhorn_kernel() {
    const int b = blockIdx.x;
    __shared__ float u_sh[NN], v_sh[MM];
    __shared__ int rc[NN], cc[MM];
    __shared__ float red[32];
    __shared__ float S_sh[2];  // [0]=S_v, [1]=S_u
    const int tid = threadIdx.x;

    for (int j = tid; j < MM; j += 1024) {
        v_sh[j] = 1.0f;
        int c = g_ccnt[b * MM + j];
        cc[j] = (c < STRIDE) ? c : STRIDE;
    }
    for (int i = tid; i < NN; i += 1024) rc[i] = g_rcnt[b * NN + i];
    if (tid == 0) S_sh[0] = (float)MM;
    __syncthreads();

    const uint2* rell = g_rell + (size_t)b * STRIDE * NN;
    const uint2* cell = g_cell + (size_t)b * STRIDE * MM;

    for (int iter = 0; iter < NITER; iter++) {
        // -------- phase A: u from v --------
        const float fv = KFLOOR * S_sh[0];
        float usum = 0.0f;
#pragma unroll
        for (int rr = 0; rr < NN / 1024; rr++) {
            const int i = rr * 1024 + tid;
            const int cnt = rc[i];
            const uint2* p = rell + i;
            float acc = 0.0f;
            int k = 0;
            for (; k + 4 <= cnt; k += 4) {
                uint2 e0 = p[(size_t)(k + 0) * NN];
                uint2 e1 = p[(size_t)(k + 1) * NN];
                uint2 e2 = p[(size_t)(k + 2) * NN];
                uint2 e3 = p[(size_t)(k + 3) * NN];
                acc = fmaf(uaf(e0.y), v_sh[e0.x], acc);
                acc = fmaf(uaf(e1.y), v_sh[e1.x], acc);
                acc = fmaf(uaf(e2.y), v_sh[e2.x], acc);
                acc = fmaf(uaf(e3.y), v_sh[e3.x], acc);
            }
            for (; k < cnt; k++) {
                uint2 e = p[(size_t)k * NN];
                acc = fmaf(uaf(e.y), v_sh[e.x], acc);
            }
            float u = MUV / fmaxf(fv + acc, EPSDIV);
            u_sh[i] = u;
            usum += u;
        }
        __syncthreads();
        float su = block_reduce_sum(usum, red);
        if (tid == 0) S_sh[1] = su;
        __syncthreads();

        // -------- phase B: v from u --------
        const float fu = KFLOOR * S_sh[1];
        float vsum = 0.0f;
#pragma unroll
        for (int rr = 0; rr < MM / 1024; rr++) {
            const int j = rr * 1024 + tid;
            const int cnt = cc[j];
            const uint2* p = cell + j;
            float acc = 0.0f;
            int k = 0;
            for (; k + 4 <= cnt; k += 4) {
                uint2 e0 = p[(size_t)(k + 0) * MM];
                uint2 e1 = p[(size_t)(k + 1) * MM];
                uint2 e2 = p[(size_t)(k + 2) * MM];
                uint2 e3 = p[(size_t)(k + 3) * MM];
                acc = fmaf(uaf(e0.y), u_sh[e0.x], acc);
                acc = fmaf(uaf(e1.y), u_sh[e1.x], acc);
                acc = fmaf(uaf(e2.y), u_sh[e2.x], acc);
                acc = fmaf(uaf(e3.y), u_sh[e3.x], acc);
            }
            for (; k < cnt; k++) {
                uint2 e = p[(size_t)k * MM];
                acc = fmaf(uaf(e.y), u_sh[e.x], acc);
            }
            float v = MUV / fmaxf(fu + acc, EPSDIV);
            v_sh[j] = v;
            vsum += v;
        }
        __syncthreads();
        float sv = block_reduce_sum(vsum, red);
        if (tid == 0) S_sh[0] = sv;
        __syncthreads();
    }

    for (int i = tid; i < NN; i += 1024) g_u[b * NN + i] = u_sh[i];
    for (int j = tid; j < MM; j += 1024) g_v[b * MM + j] = v_sh[j];
}

// ---------------------------------------------------------------------------
// Dense final reduction: emd_b = sum_ij u_i * K_ij * v_j * d_ij
__global__ void emd_kernel(const float* __restrict__ src, const float* __restrict__ tgt) {
    const int b = blockIdx.y;
    __shared__ float tx[MM], ty[MM], tz[MM], vv[MM];
    __shared__ float red[8];
    const float* T = tgt + (size_t)b * MM * 3;
    for (int j = threadIdx.x; j < MM; j += blockDim.x) {
        tx[j] = T[3 * j + 0];
        ty[j] = T[3 * j + 1];
        tz[j] = T[3 * j + 2];
        vv[j] = g_v[b * MM + j];
    }
    __syncthreads();

    const int warp = threadIdx.x >> 5, lane = threadIdx.x & 31;
    const int nwarps = blockDim.x >> 5;
    const int rows_per_cta = NN / gridDim.x;
    const int row0 = blockIdx.x * rows_per_cta;
    const float* S = src + (size_t)b * NN * 3;

    float wacc = 0.0f;
    for (int i = row0 + warp; i < row0 + rows_per_cta; i += nwarps) {
        const float sx = S[3 * i + 0], sy = S[3 * i + 1], sz = S[3 * i + 2];
        const float ui = g_u[b * NN + i];
        float racc = 0.0f;
        for (int j0 = 0; j0 < MM; j0 += 32) {
            const int j = j0 + lane;
            float dx = sx - tx[j];
            float dy = sy - ty[j];
            float dz = sz - tz[j];
            float s = fmaf(dx, dx, fmaf(dy, dy, dz * dz));
            float d = sqrtf(s);
            float K = (s < 0.25f) ? expf(-100.0f * d) : KFLOOR;
            racc = fmaf(K * d, vv[j], racc);
        }
        wacc = fmaf(ui, racc, wacc);
    }
#pragma unroll
    for (int o = 16; o > 0; o >>= 1) wacc += __shfl_xor_sync(0xffffffffu, wacc, o);
    if (lane == 0) red[warp] = wacc;
    __syncthreads();
    if (threadIdx.x == 0) {
        float s = 0.0f;
        for (int w = 0; w < (int)(blockDim.x >> 5); w++) s += red[w];
        atomicAdd(&g_accum, s);
    }
}

__global__ void finalize_kernel(float* out) { out[0] = g_accum * (1.0f / BB); }

// ---------------------------------------------------------------------------
extern "C" void kernel_launch(void* const* d_in, const int* in_sizes, int n_in,
                              void* d_out, int out_size) {
    (void)in_sizes; (void)n_in; (void)out_size;
    const float* src = (const float*)d_in[0];
    const float* tgt = (const float*)d_in[1];
    float* out = (float*)d_out;

    init_kernel<<<64, 256>>>();
    build_kernel<<<dim3(16, BB), 256>>>(src, tgt);
    sinkhorn_kernel<<<BB, 1024>>>();
    emd_kernel<<<dim3(16, BB), 256>>>(src, tgt);
    finalize_kernel<<<1, 1>>>(out);
}

// round 2
// speedup vs baseline: 3.4599x; 3.4599x over previous
#include <cuda_runtime.h>
#include <math.h>
#include <stdint.h>

#define BB 8
#define NN 2048
#define MM 2048
#define STRIDE 512            /* max sparse entries per row/col */
#define PAIRS (STRIDE / 2)    /* uint4 pair slots */
#define NITER 100
#define CL 8                  /* cluster size: CTAs per batch   */
#define SLICE (NN / CL)       /* 256 rows/cols per CTA          */

#define KFLOOR 1.9287498479639178e-22f   /* fp32(exp(-50)) */
#define MUV    4.8828125e-4f             /* 1/2048 */
#define EPSDIV 1e-8f

static __device__ __forceinline__ float uaf(unsigned x) { return __uint_as_float(x); }

// ---- static device scratch (no runtime allocations allowed) ----
// pair-packed ELL: pair slot p of row i lives at [b][p*NN + i] (uint4 = two (idx,val) entries)
__device__ uint4 g_rell4[(size_t)BB * PAIRS * NN];   // (j, Ktilde)       row-major   (Kv phase)
__device__ uint4 g_cell4[(size_t)BB * PAIRS * MM];   // (i, Ktilde)       col-major   (K^T u phase)
__device__ uint4 g_eell4[(size_t)BB * PAIRS * NN];   // (j, Ktilde * d)   row-major   (emd pass)
__device__ int   g_rcnt[BB * NN];
__device__ int   g_ccnt[BB * MM];
__device__ float g_u[BB * NN];
__device__ float g_v[BB * MM];
__device__ float g_accum;

// ---- cluster / DSMEM helpers ----
static __device__ __forceinline__ uint32_t smem_u32(const void* p) {
    return (uint32_t)__cvta_generic_to_shared(p);
}
static __device__ __forceinline__ uint32_t mapa_sh(uint32_t addr, uint32_t rank) {
    uint32_t o;
    asm("mapa.shared::cluster.u32 %0, %1, %2;" : "=r"(o) : "r"(addr), "r"(rank));
    return o;
}
static __device__ __forceinline__ void st_sh_cluster(uint32_t addr, float v) {
    asm volatile("st.shared::cluster.f32 [%0], %1;" :: "r"(addr), "f"(v) : "memory");
}
#define CLUSTER_SYNC() do {                                                 \
    asm volatile("barrier.cluster.arrive.aligned;" ::: "memory");           \
    asm volatile("barrier.cluster.wait.aligned;"   ::: "memory");           \
} while (0)

// ---------------------------------------------------------------------------
__global__ void init_kernel() {
    int t = blockIdx.x * blockDim.x + threadIdx.x;
    if (t < BB * NN) g_rcnt[t] = 0;
    if (t < BB * MM) g_ccnt[t] = 0;
    if (t == 0) g_accum = 0.0f;
}

// ---------------------------------------------------------------------------
// Build sparse correction lists where d^2 < 0.25 (i.e. 100*d < 50).
// Everywhere else K == exp(-50) exactly (same bits as the reference clamp).
__global__ void build_kernel(const float* __restrict__ src, const float* __restrict__ tgt) {
    const int b = blockIdx.y;
    __shared__ float tx[MM], ty[MM], tz[MM];
    const float* T = tgt + (size_t)b * MM * 3;
    for (int j = threadIdx.x; j < MM; j += blockDim.x) {
        tx[j] = T[3 * j + 0];
        ty[j] = T[3 * j + 1];
        tz[j] = T[3 * j + 2];
    }
    __syncthreads();

    const int warp = threadIdx.x >> 5, lane = threadIdx.x & 31;
    const int nwarps = blockDim.x >> 5;
    const int rows_per_cta = NN / gridDim.x;
    const int row0 = blockIdx.x * rows_per_cta;
    const float* S = src + (size_t)b * NN * 3;
    uint2* rell2 = (uint2*)(g_rell4 + (size_t)b * PAIRS * NN);
    uint2* eell2 = (uint2*)(g_eell4 + (size_t)b * PAIRS * NN);
    uint2* cell2 = (uint2*)(g_cell4 + (size_t)b * PAIRS * MM);

    for (int i = row0 + warp; i < row0 + rows_per_cta; i += nwarps) {
        const float sx = S[3 * i + 0], sy = S[3 * i + 1], sz = S[3 * i + 2];
        int rbase = 0;
        for (int j0 = 0; j0 < MM; j0 += 32) {
            const int j = j0 + lane;
            float dx = sx - tx[j];
            float dy = sy - ty[j];
            float dz = sz - tz[j];
            float s = fmaf(dx, dx, fmaf(dy, dy, dz * dz));
            bool pred = (s < 0.25f);
            unsigned mask = __ballot_sync(0xffffffffu, pred);
            if (pred) {
                float d = sqrtf(s);
                float kt = expf(-100.0f * d) - KFLOOR;
                int k = rbase + __popc(mask & ((1u << lane) - 1u));
                if (k < STRIDE) {
                    size_t i2 = ((size_t)(k >> 1) * NN + i) * 2 + (k & 1);
                    rell2[i2] = make_uint2((unsigned)j, __float_as_uint(kt));
                    eell2[i2] = make_uint2((unsigned)j, __float_as_uint(kt * d));
                }
                int kc = atomicAdd(&g_ccnt[b * MM + j], 1);
                if (kc < STRIDE)
                    cell2[((size_t)(kc >> 1) * MM + j) * 2 + (kc & 1)] =
                        make_uint2((unsigned)i, __float_as_uint(kt));
            }
            rbase += __popc(mask);
        }
        int cap = (rbase < STRIDE) ? rbase : STRIDE;
        if (lane == 0) {
            g_rcnt[b * NN + i] = cap;
            if (cap < STRIDE && (cap & 1)) {  // zero-pad odd tail so pair reads are exact
                size_t i2 = ((size_t)(cap >> 1) * NN + i) * 2 + 1;
                rell2[i2] = make_uint2(0u, 0u);
                eell2[i2] = make_uint2(0u, 0u);
            }
        }
    }
}

// Clamp column counts + zero-pad odd tails of the column lists.
__global__ void colfix_kernel() {
    int t = blockIdx.x * blockDim.x + threadIdx.x;
    if (t >= BB * MM) return;
    int c = g_ccnt[t];
    if (c > STRIDE) c = STRIDE;
    g_ccnt[t] = c;
    if (c & 1) {
        int b = t / MM, j = t - b * MM;
        uint2* cell2 = (uint2*)(g_cell4 + (size_t)b * PAIRS * MM);
        cell2[((size_t)(c >> 1) * MM + j) * 2 + 1] = make_uint2(0u, 0u);
    }
}

// ---------------------------------------------------------------------------
__device__ __forceinline__ float block_reduce_sum(float val, float* red) {
#pragma unroll
    for (int o = 16; o > 0; o >>= 1) val += __shfl_xor_sync(0xffffffffu, val, o);
    const int lane = threadIdx.x & 31, warp = threadIdx.x >> 5;
    if (lane == 0) red[warp] = val;
    __syncthreads();
    float r = 0.0f;
    if (warp == 0) {
        r = red[lane];  // exactly 32 warps (1024 threads)
#pragma unroll
        for (int o = 16; o > 0; o >>= 1) r += __shfl_xor_sync(0xffffffffu, r, o);
    }
    return r;  // valid on warp 0
}

// ---------------------------------------------------------------------------
// One 8-CTA cluster per batch; each CTA owns a 256-row + 256-col slice.
// Full u/v replicated in every CTA's SMEM via DSMEM broadcast each phase.
//   u_i = mu / max(KFLOOR*S_v + sparse_row_i . v, 1e-8)
//   v_j = nu / max(KFLOOR*S_u + sparse_col_j . u, 1e-8)
__global__ void __launch_bounds__(1024, 1) __cluster_dims__(CL, 1, 1)
sinkhorn_kernel() {
    const int b = blockIdx.x >> 3;
    uint32_t crank;
    asm("mov.u32 %0, %%cluster_ctarank;" : "=r"(crank));
    const int tid = threadIdx.x;
    const int row0 = (int)crank * SLICE;

    __shared__ float u_sh[NN], v_sh[MM];
    __shared__ float part[1024];
    __shared__ float red[32];
    __shared__ float SpU[CL], SpV[CL];
    __shared__ int rc_sh[SLICE], cc_sh[SLICE];

    for (int j = tid; j < MM; j += 1024) v_sh[j] = 1.0f;
    if (tid < SLICE) {
        rc_sh[tid] = g_rcnt[b * NN + row0 + tid];
        cc_sh[tid] = g_ccnt[b * MM + row0 + tid];
    }
    __syncthreads();

    const uint4* rell = g_rell4 + (size_t)b * PAIRS * NN;
    const uint4* cell = g_cell4 + (size_t)b * PAIRS * MM;
    const uint32_t u_base = smem_u32(u_sh);
    const uint32_t v_base = smem_u32(v_sh);
    const uint32_t spu_base = smem_u32(SpU);
    const uint32_t spv_base = smem_u32(SpV);

    const int lrow = tid & (SLICE - 1);  // 0..255
    const int sub  = tid >> 8;           // 0..3

    float fv = KFLOOR * (float)MM;       // S_v = 2048 at iter 0 (v = 1)
    float fu;

    for (int iter = 0; iter < NITER; iter++) {
        // ---------------- phase A: u from v ----------------
        {
            const int npairs = (rc_sh[lrow] + 1) >> 1;
            const uint4* p = rell + (row0 + lrow);
            float acc = 0.0f;
#pragma unroll 2
            for (int pp = sub; pp < npairs; pp += 4) {
                uint4 e = p[(size_t)pp * NN];
                acc = fmaf(uaf(e.y), v_sh[e.x], acc);
                acc = fmaf(uaf(e.w), v_sh[e.z], acc);
            }
            part[tid] = acc;
        }
        __syncthreads();
        float u = 0.0f;
        if (tid < SLICE) {
            float tot = part[tid] + part[tid + 256] + part[tid + 512] + part[tid + 768];
            u = MUV / fmaxf(fv + tot, EPSDIV);
            u_sh[row0 + tid] = u;
        }
        float su = block_reduce_sum(u, red);       // contains __syncthreads
        if (tid < CL) st_sh_cluster(mapa_sh(spu_base + crank * 4, (uint32_t)tid), su);
        {   // broadcast my 256 u values to every CTA's replicated u_sh
            float val = u_sh[row0 + lrow];
            uint32_t la = u_base + (uint32_t)(row0 + lrow) * 4;
            st_sh_cluster(mapa_sh(la, (uint32_t)sub), val);
            st_sh_cluster(mapa_sh(la, (uint32_t)(sub + 4)), val);
        }
        CLUSTER_SYNC();
        fu = KFLOOR * (SpU[0] + SpU[1] + SpU[2] + SpU[3] +
                       SpU[4] + SpU[5] + SpU[6] + SpU[7]);

        // ---------------- phase B: v from u ----------------
        {
            const int npairs = (cc_sh[lrow] + 1) >> 1;
            const uint4* p = cell + (row0 + lrow);
            float acc = 0.0f;
#pragma unroll 2
            for (int pp = sub; pp < npairs; pp += 4) {
                uint4 e = p[(size_t)pp * MM];
                acc = fmaf(uaf(e.y), u_sh[e.x], acc);
                acc = fmaf(uaf(e.w), u_sh[e.z], acc);
            }
            part[tid] = acc;
        }
        __syncthreads();
        float v = 0.0f;
        if (tid < SLICE) {
            float tot = part[tid] + part[tid + 256] + part[tid + 512] + part[tid + 768];
            v = MUV / fmaxf(fu + tot, EPSDIV);
            v_sh[row0 + tid] = v;
        }
        float sv = block_reduce_sum(v, red);
        if (tid < CL) st_sh_cluster(mapa_sh(spv_base + crank * 4, (uint32_t)tid), sv);
        {
            float val = v_sh[row0 + lrow];
            uint32_t la = v_base + (uint32_t)(row0 + lrow) * 4;
            st_sh_cluster(mapa_sh(la, (uint32_t)sub), val);
            st_sh_cluster(mapa_sh(la, (uint32_t)(sub + 4)), val);
        }
        CLUSTER_SYNC();
        fv = KFLOOR * (SpV[0] + SpV[1] + SpV[2] + SpV[3] +
                       SpV[4] + SpV[5] + SpV[6] + SpV[7]);
    }

    if (tid < SLICE) {
        g_u[b * NN + row0 + tid] = u_sh[row0 + tid];
        g_v[b * MM + row0 + tid] = v_sh[row0 + tid];
    }
}

// ---------------------------------------------------------------------------
// emd_b = sum_ij u_i K_ij d_ij v_j
//       = sum_i u_i * ( KFLOOR * sum_j d_ij v_j  +  sum_sparse (K~d)_ij v_j )
// Dense part is branchless (no exp); sparse part reuses the pair-packed list.
__global__ void emd_kernel(const float* __restrict__ src, const float* __restrict__ tgt) {
    const int b = blockIdx.y;
    __shared__ float tx[MM], ty[MM], tz[MM], vv[MM];
    __shared__ float redw[8];
    const float* T = tgt + (size_t)b * MM * 3;
    for (int j = threadIdx.x; j < MM; j += blockDim.x) {
        tx[j] = T[3 * j + 0];
        ty[j] = T[3 * j + 1];
        tz[j] = T[3 * j + 2];
        vv[j] = g_v[b * MM + j];
    }
    __syncthreads();

    const int warp = threadIdx.x >> 5, lane = threadIdx.x & 31;
    const int nwarps = blockDim.x >> 5;
    const int rows_per_cta = NN / gridDim.x;
    const int row0 = blockIdx.x * rows_per_cta;
    const float* S = src + (size_t)b * NN * 3;
    const uint4* eell = g_eell4 + (size_t)b * PAIRS * NN;

    float wacc = 0.0f;
    for (int i = row0 + warp; i < row0 + rows_per_cta; i += nwarps) {
        const float sx = S[3 * i + 0], sy = S[3 * i + 1], sz = S[3 * i + 2];
        const float ui = g_u[b * NN + i];
        float dacc = 0.0f;
        for (int j0 = 0; j0 < MM; j0 += 32) {
            const int j = j0 + lane;
            float dx = sx - tx[j];
            float dy = sy - ty[j];
            float dz = sz - tz[j];
            float s = fmaf(dx, dx, fmaf(dy, dy, dz * dz));
            dacc = fmaf(sqrtf(s), vv[j], dacc);
        }
        float sacc = 0.0f;
        const int npairs = (g_rcnt[b * NN + i] + 1) >> 1;
        const uint4* p = eell + i;
        for (int pp = lane; pp < npairs; pp += 32) {
            uint4 e = p[(size_t)pp * NN];
            sacc = fmaf(uaf(e.y), vv[e.x], sacc);
            sacc = fmaf(uaf(e.w), vv[e.z], sacc);
        }
        float tot = fmaf(KFLOOR, dacc, sacc);
#pragma unroll
        for (int o = 16; o > 0; o >>= 1) tot += __shfl_xor_sync(0xffffffffu, tot, o);
        if (lane == 0) wacc = fmaf(ui, tot, wacc);
    }
    if (lane == 0) redw[warp] = wacc;
    __syncthreads();
    if (threadIdx.x == 0) {
        float s = 0.0f;
        for (int w = 0; w < nwarps; w++) s += redw[w];
        atomicAdd(&g_accum, s);
    }
}

__global__ void finalize_kernel(float* out) { out[0] = g_accum * (1.0f / BB); }

// ---------------------------------------------------------------------------
extern "C" void kernel_launch(void* const* d_in, const int* in_sizes, int n_in,
                              void* d_out, int out_size) {
    (void)in_sizes; (void)n_in; (void)out_size;
    const float* src = (const float*)d_in[0];
    const float* tgt = (const float*)d_in[1];
    float* out = (float*)d_out;

    init_kernel<<<64, 256>>>();
    build_kernel<<<dim3(32, BB), 256>>>(src, tgt);
    colfix_kernel<<<64, 256>>>();
    sinkhorn_kernel<<<BB * CL, 1024>>>();
    emd_kernel<<<dim3(64, BB), 256>>>(src, tgt);
    finalize_kernel<<<1, 1>>>(out);
}

// round 3
// speedup vs baseline: 3.7851x; 1.0940x over previous
#include <cuda_runtime.h>
#include <math.h>
#include <stdint.h>

#define BB 8
#define NN 2048
#define MM 2048
#define STRIDE 512            /* max sparse entries per row/col */
#define PAIRS (STRIDE / 2)    /* uint4 pair slots */
#define NITER 100
#define CL 8                  /* cluster size: CTAs per batch   */
#define SLICE 256             /* rows/cols per CTA              */
#define TXB 8448u             /* per-phase incoming bytes: 2048*4 + 64*4 */

#define KFLOOR 1.9287498479639178e-22f   /* fp32(exp(-50)) */
#define MUV    4.8828125e-4f             /* 1/2048 */
#define EPSDIV 1e-8f

static __device__ __forceinline__ float uaf(unsigned x) { return __uint_as_float(x); }

// ---- static device scratch (no runtime allocations allowed) ----
__device__ uint4 g_rell4[(size_t)BB * PAIRS * NN];   // (j, Ktilde)     row-major (Kv phase)
__device__ uint4 g_cell4[(size_t)BB * PAIRS * MM];   // (i, Ktilde)     col-major (K^T u phase)
__device__ uint4 g_eell4[(size_t)BB * PAIRS * NN];   // (j, Ktilde*d)   row-major (emd pass)
__device__ int   g_rcnt[BB * NN];
__device__ int   g_ccnt[BB * MM];
__device__ float g_u[BB * NN];
__device__ float g_v[BB * MM];
__device__ float g_accum;

// ---- cluster / DSMEM / mbarrier helpers ----
static __device__ __forceinline__ uint32_t smem_u32(const void* p) {
    return (uint32_t)__cvta_generic_to_shared(p);
}
static __device__ __forceinline__ uint32_t mapa_sh(uint32_t addr, uint32_t rank) {
    uint32_t o;
    asm("mapa.shared::cluster.u32 %0, %1, %2;" : "=r"(o) : "r"(addr), "r"(rank));
    return o;
}
static __device__ __forceinline__ void st_async32(uint32_t daddr, unsigned v, uint32_t dmbar) {
    asm volatile("st.async.shared::cluster.mbarrier::complete_tx::bytes.u32 [%0], %1, [%2];"
                 :: "r"(daddr), "r"(v), "r"(dmbar) : "memory");
}
static __device__ __forceinline__ void st_async64(uint32_t daddr, unsigned long long v, uint32_t dmbar) {
    asm volatile("st.async.shared::cluster.mbarrier::complete_tx::bytes.u64 [%0], %1, [%2];"
                 :: "r"(daddr), "l"(v), "r"(dmbar) : "memory");
}
static __device__ __forceinline__ void mb_init(uint32_t mb, uint32_t cnt) {
    asm volatile("mbarrier.init.shared.b64 [%0], %1;" :: "r"(mb), "r"(cnt) : "memory");
}
static __device__ __forceinline__ void mb_expect(uint32_t mb, uint32_t tx) {
    asm volatile("mbarrier.arrive.expect_tx.shared.b64 _, [%0], %1;" :: "r"(mb), "r"(tx) : "memory");
}
static __device__ __forceinline__ void mb_wait(uint32_t mb, uint32_t parity) {
    uint32_t done;
    asm volatile("{\n\t.reg .pred p;\n\t"
                 "mbarrier.try_wait.parity.acquire.cluster.shared::cta.b64 p, [%1], %2;\n\t"
                 "selp.b32 %0, 1, 0, p;\n\t}"
                 : "=r"(done) : "r"(mb), "r"(parity) : "memory");
    while (!done) {
        asm volatile("{\n\t.reg .pred p;\n\t"
                     "mbarrier.try_wait.parity.acquire.cluster.shared::cta.b64 p, [%1], %2, 0x989680;\n\t"
                     "selp.b32 %0, 1, 0, p;\n\t}"
                     : "=r"(done) : "r"(mb), "r"(parity) : "memory");
    }
}
#define CLUSTER_SYNC() do {                                                 \
    asm volatile("barrier.cluster.arrive.aligned;" ::: "memory");           \
    asm volatile("barrier.cluster.wait.aligned;"   ::: "memory");           \
} while (0)

// ---------------------------------------------------------------------------
__global__ void init_kernel() {
    int t = blockIdx.x * blockDim.x + threadIdx.x;
    if (t < BB * NN) g_rcnt[t] = 0;
    if (t < BB * MM) g_ccnt[t] = 0;
    if (t == 0) g_accum = 0.0f;
}

// ---------------------------------------------------------------------------
// Build sparse correction lists where d^2 < 0.25 (i.e. 100*d < 50).
// Everywhere else K == exp(-50) exactly (same bits as the reference clamp).
__global__ void build_kernel(const float* __restrict__ src, const float* __restrict__ tgt) {
    const int b = blockIdx.y;
    __shared__ float tx[MM], ty[MM], tz[MM];
    const float* T = tgt + (size_t)b * MM * 3;
    for (int j = threadIdx.x; j < MM; j += blockDim.x) {
        tx[j] = T[3 * j + 0];
        ty[j] = T[3 * j + 1];
        tz[j] = T[3 * j + 2];
    }
    __syncthreads();

    const int warp = threadIdx.x >> 5, lane = threadIdx.x & 31;
    const int nwarps = blockDim.x >> 5;
    const int rows_per_cta = NN / gridDim.x;
    const int row0 = blockIdx.x * rows_per_cta;
    const float* S = src + (size_t)b * NN * 3;
    uint2* rell2 = (uint2*)(g_rell4 + (size_t)b * PAIRS * NN);
    uint2* eell2 = (uint2*)(g_eell4 + (size_t)b * PAIRS * NN);
    uint2* cell2 = (uint2*)(g_cell4 + (size_t)b * PAIRS * MM);

    for (int i = row0 + warp; i < row0 + rows_per_cta; i += nwarps) {
        const float sx = S[3 * i + 0], sy = S[3 * i + 1], sz = S[3 * i + 2];
        int rbase = 0;
        for (int j0 = 0; j0 < MM; j0 += 32) {
            const int j = j0 + lane;
            float dx = sx - tx[j];
            float dy = sy - ty[j];
            float dz = sz - tz[j];
            float s = fmaf(dx, dx, fmaf(dy, dy, dz * dz));
            bool pred = (s < 0.25f);
            unsigned mask = __ballot_sync(0xffffffffu, pred);
            if (pred) {
                float d = sqrtf(s);
                float kt = expf(-100.0f * d) - KFLOOR;
                int k = rbase + __popc(mask & ((1u << lane) - 1u));
                if (k < STRIDE) {
                    size_t i2 = ((size_t)(k >> 1) * NN + i) * 2 + (k & 1);
                    rell2[i2] = make_uint2((unsigned)j, __float_as_uint(kt));
                    eell2[i2] = make_uint2((unsigned)j, __float_as_uint(kt * d));
                }
                int kc = atomicAdd(&g_ccnt[b * MM + j], 1);
                if (kc < STRIDE)
                    cell2[((size_t)(kc >> 1) * MM + j) * 2 + (kc & 1)] =
                        make_uint2((unsigned)i, __float_as_uint(kt));
            }
            rbase += __popc(mask);
        }
        int cap = (rbase < STRIDE) ? rbase : STRIDE;
        if (lane == 0) {
            g_rcnt[b * NN + i] = cap;
            if (cap < STRIDE && (cap & 1)) {  // zero-pad odd tail so pair reads are exact
                size_t i2 = ((size_t)(cap >> 1) * NN + i) * 2 + 1;
                rell2[i2] = make_uint2(0u, 0u);
                eell2[i2] = make_uint2(0u, 0u);
            }
        }
    }
}

// Clamp column counts + zero-pad odd tails of the column lists.
__global__ void colfix_kernel() {
    int t = blockIdx.x * blockDim.x + threadIdx.x;
    if (t >= BB * MM) return;
    int c = g_ccnt[t];
    if (c > STRIDE) c = STRIDE;
    g_ccnt[t] = c;
    if (c & 1) {
        int b = t / MM, j = t - b * MM;
        uint2* cell2 = (uint2*)(g_cell4 + (size_t)b * PAIRS * MM);
        cell2[((size_t)(c >> 1) * MM + j) * 2 + 1] = make_uint2(0u, 0u);
    }
}

// ---------------------------------------------------------------------------
// One 8-CTA cluster per batch; each CTA owns a 256-row + 256-col slice; full
// u/v replicated in every CTA's SMEM. Broadcast via st.async (tx-counted
// mbarrier completion) — NO per-phase cluster barrier, so L1 stays warm and
// sync cost is a single mbarrier wakeup per phase.
__global__ void __launch_bounds__(1024, 1) __cluster_dims__(CL, 1, 1)
sinkhorn_kernel() {
    const int b = blockIdx.x >> 3;
    uint32_t crank;
    asm("mov.u32 %0, %%cluster_ctarank;" : "=r"(crank));
    const int tid = threadIdx.x;
    const int row0 = (int)crank * SLICE;

    __shared__ float u_sh[NN], v_sh[MM];
    __shared__ float part[1024];
    __shared__ float slotsU[64], slotsV[64];
    __shared__ float fscale[2];        // [0] = KFLOOR*S_v, [1] = KFLOOR*S_u
    __shared__ int rc_sh[SLICE], cc_sh[SLICE];
    __shared__ unsigned long long mbU_s, mbV_s;

    const uint32_t mbu = smem_u32(&mbU_s), mbv = smem_u32(&mbV_s);
    const uint32_t u_base = smem_u32(u_sh), v_base = smem_u32(v_sh);
    const uint32_t sU_base = smem_u32(slotsU), sV_base = smem_u32(slotsV);

    if (tid == 0) {
        mb_init(mbu, 1);
        mb_init(mbv, 1);
        fscale[0] = KFLOOR * (float)MM;   // S_v = 2048 at iter 0 (v = 1)
    }
    for (int j = tid; j < MM; j += 1024) v_sh[j] = 1.0f;
    if (tid < SLICE) {
        rc_sh[tid] = g_rcnt[b * NN + row0 + tid];
        cc_sh[tid] = g_ccnt[b * MM + row0 + tid];
    }
    __syncthreads();
    CLUSTER_SYNC();   // peers' mbarriers + v_sh init visible before any st.async lands

    const uint4* rell = g_rell4 + (size_t)b * PAIRS * NN;
    const uint4* cell = g_cell4 + (size_t)b * PAIRS * MM;
    const int lrow = tid & 255;       // 0..255
    const int sub  = tid >> 8;        // 0..3
    const uint4* prow = rell + (row0 + lrow);
    const uint4* pcol = cell + (row0 + lrow);
    const int rnp = (rc_sh[lrow] + 1) >> 1;
    const int cnp = (cc_sh[lrow] + 1) >> 1;

    for (int iter = 0; iter < NITER; iter++) {
        const uint32_t par = (uint32_t)(iter & 1);

        // ---------------- phase A: u from v ----------------
        if (tid == 0) mb_expect(mbu, TXB);
        {
            float acc = 0.0f;
            for (int pp = sub; pp < rnp; pp += 4) {
                uint4 e = prow[(size_t)pp * NN];
                acc = fmaf(uaf(e.y), v_sh[e.x], acc);
                acc = fmaf(uaf(e.w), v_sh[e.z], acc);
            }
            part[tid] = acc;
        }
        __syncthreads();   // publishes part[] and fscale[0]
        if (tid < SLICE) {
            float tot = part[tid] + part[tid + 256] + part[tid + 512] + part[tid + 768];
            float u = MUV / fmaxf(fscale[0] + tot, EPSDIV);
            float ws = u;
#pragma unroll
            for (int o = 16; o > 0; o >>= 1) ws += __shfl_xor_sync(0xffffffffu, ws, o);
            float uhi = __shfl_down_sync(0xffffffffu, u, 1);
            if (!(tid & 1)) {   // b64-paired broadcast of (u[i], u[i+1]) to all 8 ranks
                unsigned long long pk =
                    ((unsigned long long)__float_as_uint(uhi) << 32) | __float_as_uint(u);
                uint32_t la = u_base + (uint32_t)(row0 + tid) * 4;
#pragma unroll
                for (uint32_t r = 0; r < 8; r++)
                    st_async64(mapa_sh(la, r), pk, mapa_sh(mbu, r));
            }
            if (!(tid & 31)) {  // per-warp partial of S_u -> 64 slots on every rank
                uint32_t sa = sU_base + (crank * 8u + (uint32_t)(tid >> 5)) * 4u;
                float wsv = ws;
#pragma unroll
                for (uint32_t r = 0; r < 8; r++)
                    st_async32(mapa_sh(sa, r), __float_as_uint(wsv), mapa_sh(mbu, r));
            }
        }
        mb_wait(mbu, par);
        if (tid < 32) {   // fu for phase B; published by phase B's __syncthreads
            float s = slotsU[tid] + slotsU[tid + 32];
#pragma unroll
            for (int o = 16; o > 0; o >>= 1) s += __shfl_xor_sync(0xffffffffu, s, o);
            if (tid == 0) fscale[1] = KFLOOR * s;
        }

        // ---------------- phase B: v from u ----------------
        if (tid == 0) mb_expect(mbv, TXB);
        {
            float acc = 0.0f;
            for (int pp = sub; pp < cnp; pp += 4) {
                uint4 e = pcol[(size_t)pp * MM];
                acc = fmaf(uaf(e.y), u_sh[e.x], acc);
                acc = fmaf(uaf(e.w), u_sh[e.z], acc);
            }
            part[tid] = acc;
        }
        __syncthreads();   // publishes part[] and fscale[1]
        if (tid < SLICE) {
            float tot = part[tid] + part[tid + 256] + part[tid + 512] + part[tid + 768];
            float v = MUV / fmaxf(fscale[1] + tot, EPSDIV);
            float ws = v;
#pragma unroll
            for (int o = 16; o > 0; o >>= 1) ws += __shfl_xor_sync(0xffffffffu, ws, o);
            float vhi = __shfl_down_sync(0xffffffffu, v, 1);
            if (!(tid & 1)) {
                unsigned long long pk =
                    ((unsigned long long)__float_as_uint(vhi) << 32) | __float_as_uint(v);
                uint32_t la = v_base + (uint32_t)(row0 + tid) * 4;
#pragma unroll
                for (uint32_t r = 0; r < 8; r++)
                    st_async64(mapa_sh(la, r), pk, mapa_sh(mbv, r));
            }
            if (!(tid & 31)) {
                uint32_t sa = sV_base + (crank * 8u + (uint32_t)(tid >> 5)) * 4u;
                float wsv = ws;
#pragma unroll
                for (uint32_t r = 0; r < 8; r++)
                    st_async32(mapa_sh(sa, r), __float_as_uint(wsv), mapa_sh(mbv, r));
            }
        }
        mb_wait(mbv, par);
        if (tid < 32) {   // fv for next phase A; published by its __syncthreads
            float s = slotsV[tid] + slotsV[tid + 32];
#pragma unroll
            for (int o = 16; o > 0; o >>= 1) s += __shfl_xor_sync(0xffffffffu, s, o);
            if (tid == 0) fscale[0] = KFLOOR * s;
        }
    }

    if (tid < SLICE) {
        g_u[b * NN + row0 + tid] = u_sh[row0 + tid];
        g_v[b * MM + row0 + tid] = v_sh[row0 + tid];
    }
    __syncthreads();
    CLUSTER_SYNC();   // clean teardown: no CTA exits with peer traffic outstanding
}

// ---------------------------------------------------------------------------
// emd_b = sum_ij u_i K_ij d_ij v_j
//       = sum_i u_i * ( KFLOOR * sum_j d_ij v_j  +  sum_sparse (K~d)_ij v_j )
__global__ void emd_kernel(const float* __restrict__ src, const float* __restrict__ tgt) {
    const int b = blockIdx.y;
    __shared__ float tx[MM], ty[MM], tz[MM], vv[MM];
    __shared__ float redw[8];
    const float* T = tgt + (size_t)b * MM * 3;
    for (int j = threadIdx.x; j < MM; j += blockDim.x) {
        tx[j] = T[3 * j + 0];
        ty[j] = T[3 * j + 1];
        tz[j] = T[3 * j + 2];
        vv[j] = g_v[b * MM + j];
    }
    __syncthreads();

    const int warp = threadIdx.x >> 5, lane = threadIdx.x & 31;
    const int nwarps = blockDim.x >> 5;
    const int rows_per_cta = NN / gridDim.x;
    const int row0 = blockIdx.x * rows_per_cta;
    const float* S = src + (size_t)b * NN * 3;
    const uint4* eell = g_eell4 + (size_t)b * PAIRS * NN;

    float wacc = 0.0f;
    for (int i = row0 + warp; i < row0 + rows_per_cta; i += nwarps) {
        const float sx = S[3 * i + 0], sy = S[3 * i + 1], sz = S[3 * i + 2];
        const float ui = g_u[b * NN + i];
        float dacc = 0.0f;
        for (int j0 = 0; j0 < MM; j0 += 32) {
            const int j = j0 + lane;
            float dx = sx - tx[j];
            float dy = sy - ty[j];
            float dz = sz - tz[j];
            float s = fmaf(dx, dx, fmaf(dy, dy, dz * dz));
            dacc = fmaf(sqrtf(s), vv[j], dacc);
        }
        float sacc = 0.0f;
        const int npairs = (g_rcnt[b * NN + i] + 1) >> 1;
        const uint4* p = eell + i;
        for (int pp = lane; pp < npairs; pp += 32) {
            uint4 e = p[(size_t)pp * NN];
            sacc = fmaf(uaf(e.y), vv[e.x], sacc);
            sacc = fmaf(uaf(e.w), vv[e.z], sacc);
        }
        float tot = fmaf(KFLOOR, dacc, sacc);
#pragma unroll
        for (int o = 16; o > 0; o >>= 1) tot += __shfl_xor_sync(0xffffffffu, tot, o);
        if (lane == 0) wacc = fmaf(ui, tot, wacc);
    }
    if (lane == 0) redw[warp] = wacc;
    __syncthreads();
    if (threadIdx.x == 0) {
        float s = 0.0f;
        for (int w = 0; w < nwarps; w++) s += redw[w];
        atomicAdd(&g_accum, s);
    }
}

__global__ void finalize_kernel(float* out) { out[0] = g_accum * (1.0f / BB); }

// ---------------------------------------------------------------------------
extern "C" void kernel_launch(void* const* d_in, const int* in_sizes, int n_in,
                              void* d_out, int out_size) {
    (void)in_sizes; (void)n_in; (void)out_size;
    const float* src = (const float*)d_in[0];
    const float* tgt = (const float*)d_in[1];
    float* out = (float*)d_out;

    init_kernel<<<64, 256>>>();
    build_kernel<<<dim3(64, BB), 256>>>(src, tgt);
    colfix_kernel<<<64, 256>>>();
    sinkhorn_kernel<<<BB * CL, 1024>>>();
    emd_kernel<<<dim3(64, BB), 256>>>(src, tgt);
    finalize_kernel<<<1, 1>>>(out);
}